// round 2
// baseline (speedup 1.0000x reference)
#include <cuda_runtime.h>
#include <cuda_bf16.h>

// GraphSAGE 2-layer, N=100000 nodes, E=1600000 edges, D=128 throughout.
// CSR build once per call; warp-per-node mean aggregation (no float atomics);
// fused GEMM out = [mean|feat] @ [Wl|Wr]^T + b with packed fma.rn.f32x2 and
// weights resident in shared memory.
// Edge dtype (int32 vs int64) is detected ON DEVICE: JAX without x64 silently
// downcasts int64->int32, so we must handle both layouts.

#define N_NODES 100000
#define N_EDGES 1600000
#define DFEAT   128

// ---------------- scratch (device globals; no allocation allowed) ----------
__device__ int   g_is_i64;
__device__ int   g_src[N_EDGES];
__device__ int   g_dst[N_EDGES];
__device__ int   g_cursor[N_NODES];
__device__ int   g_rowptr[N_NODES + 1];
__device__ int   g_col[N_EDGES];
__device__ float g_mean[(size_t)N_NODES * DFEAT];
__device__ float g_h[(size_t)N_NODES * DFEAT];

// ---------------- small helpers -------------------------------------------
__device__ __forceinline__ unsigned long long dup_f32x2(float a) {
    unsigned long long r;
    asm("mov.b64 %0, {%1, %1};" : "=l"(r) : "f"(a));
    return r;
}
__device__ __forceinline__ void unpack_f32x2(unsigned long long v, float& lo, float& hi) {
    asm("mov.b64 {%0, %1}, %2;" : "=f"(lo), "=f"(hi) : "l"(v));
}
#define FFMA2(d, a, b, c) \
    asm("fma.rn.f32x2 %0, %1, %2, %3;" : "=l"(d) : "l"(a), "l"(b), "l"(c))

__device__ __forceinline__ int clamp_node(int v, int n) {
    unsigned u = (unsigned)v;
    return (u < (unsigned)n) ? v : 0;
}

// ---------------- edge dtype detect + extract -------------------------------
// int64 little-endian with values < 2^31: every odd 32-bit word is 0.
// int32 random node ids: odd words are random (P[all 64 zero] ~ 1e-320).
__global__ void detect_kernel(const int* __restrict__ ew) {
    int flag = 0;
    for (int i = 1; i < 128; i += 2) flag |= ew[i];
    g_is_i64 = (flag == 0) ? 1 : 0;
}

__global__ void convert_kernel(const int* __restrict__ ew, int nedges, int nnodes) {
    int e = blockIdx.x * blockDim.x + threadIdx.x;
    if (e >= nedges) return;
    int s, d;
    if (g_is_i64) {
        s = ew[2 * (size_t)e];
        d = ew[2 * ((size_t)nedges + e)];
    } else {
        s = ew[e];
        d = ew[(size_t)nedges + e];
    }
    g_src[e] = clamp_node(s, nnodes);
    g_dst[e] = clamp_node(d, nnodes);
}

// ---------------- CSR build ------------------------------------------------
__global__ void zero_int_kernel(int* p, int n) {
    int i = blockIdx.x * blockDim.x + threadIdx.x;
    if (i < n) p[i] = 0;
}

__global__ void count_deg_kernel(int nedges) {
    int e = blockIdx.x * blockDim.x + threadIdx.x;
    if (e >= nedges) return;
    atomicAdd(&g_cursor[g_dst[e]], 1);
}

// Single-CTA exclusive scan of g_cursor[0..n) -> g_rowptr[0..n], 1024 threads.
__global__ void scan_kernel(int n) {
    __shared__ int ssum[1024];
    int t = threadIdx.x;
    int chunk = (n + 1023) / 1024;
    int lo = t * chunk;
    int hi = min(lo + chunk, n);
    int s = 0;
    for (int i = lo; i < hi; ++i) s += g_cursor[i];
    ssum[t] = s;
    __syncthreads();
    for (int off = 1; off < 1024; off <<= 1) {
        int v = (t >= off) ? ssum[t - off] : 0;
        __syncthreads();
        ssum[t] += v;
        __syncthreads();
    }
    int run = (t == 0) ? 0 : ssum[t - 1];
    for (int i = lo; i < hi; ++i) {
        g_rowptr[i] = run;
        run += g_cursor[i];
    }
    if (t == 0) g_rowptr[n] = ssum[1023];
}

__global__ void fill_csr_kernel(int nedges) {
    int e = blockIdx.x * blockDim.x + threadIdx.x;
    if (e >= nedges) return;
    int dst = g_dst[e];
    int pos = g_rowptr[dst] + atomicAdd(&g_cursor[dst], 1);
    g_col[pos] = g_src[e];
}

// ---------------- mean aggregation: one warp per node ----------------------
__global__ void agg_mean_kernel(const float* __restrict__ feat, int nnodes) {
    int gwarp = (blockIdx.x * blockDim.x + threadIdx.x) >> 5;
    int lane = threadIdx.x & 31;
    if (gwarp >= nnodes) return;

    int start = g_rowptr[gwarp];
    int end = g_rowptr[gwarp + 1];
    float ax = 0.f, ay = 0.f, az = 0.f, aw = 0.f;
    int lane4 = lane * 4;

    for (int base = start; base < end; base += 32) {
        int m = min(32, end - base);
        int sv = (lane < m) ? g_col[base + lane] : 0;
        int kk = 0;
        for (; kk + 4 <= m; kk += 4) {
            int s0 = __shfl_sync(0xffffffffu, sv, kk);
            int s1 = __shfl_sync(0xffffffffu, sv, kk + 1);
            int s2 = __shfl_sync(0xffffffffu, sv, kk + 2);
            int s3 = __shfl_sync(0xffffffffu, sv, kk + 3);
            float4 v0 = *reinterpret_cast<const float4*>(feat + (size_t)s0 * DFEAT + lane4);
            float4 v1 = *reinterpret_cast<const float4*>(feat + (size_t)s1 * DFEAT + lane4);
            float4 v2 = *reinterpret_cast<const float4*>(feat + (size_t)s2 * DFEAT + lane4);
            float4 v3 = *reinterpret_cast<const float4*>(feat + (size_t)s3 * DFEAT + lane4);
            ax += v0.x + v1.x + v2.x + v3.x;
            ay += v0.y + v1.y + v2.y + v3.y;
            az += v0.z + v1.z + v2.z + v3.z;
            aw += v0.w + v1.w + v2.w + v3.w;
        }
        for (; kk < m; ++kk) {
            int s = __shfl_sync(0xffffffffu, sv, kk);
            float4 v = *reinterpret_cast<const float4*>(feat + (size_t)s * DFEAT + lane4);
            ax += v.x; ay += v.y; az += v.z; aw += v.w;
        }
    }
    float inv = 1.f / fmaxf((float)(end - start), 1.f);
    float4 o;
    o.x = ax * inv; o.y = ay * inv; o.z = az * inv; o.w = aw * inv;
    *reinterpret_cast<float4*>(g_mean + (size_t)gwarp * DFEAT + lane4) = o;
}

// ---------------- fused SAGE GEMM ------------------------------------------
// out[n][j] = sum_k mean[n][k]*Wl[j][k] + sum_k feat[n][k]*Wr[j][k] + b[j]
// CTA: 512 threads (16 warps), 8 nodes per warp -> 128 nodes / CTA.
// smem holds transposed [Wl;Wr] as sW[k][j], k in [0,256), padded stride 132.
#define W_STRIDE 132
#define GEMM_SMEM (256 * W_STRIDE * 4)

__global__ void __launch_bounds__(512)
sage_gemm_kernel(const float* __restrict__ A0,   // mean  (k = 0..127)
                 const float* __restrict__ A1,   // feat  (k = 128..255)
                 const float* __restrict__ Wl,
                 const float* __restrict__ Wr,
                 const float* __restrict__ bias,
                 float* __restrict__ out,
                 int nnodes, int relu) {
    extern __shared__ float sW[];
    int tid = threadIdx.x;
    for (int idx = tid; idx < 128 * 128; idx += 512) {
        int j = idx >> 7;
        int k = idx & 127;
        float wl = Wl[idx];
        float wr = Wr[idx];
        sW[k * W_STRIDE + j] = wl;
        sW[(k + 128) * W_STRIDE + j] = wr;
    }
    __syncthreads();

    int lane = tid & 31;
    int warp = tid >> 5;
    long long base_node = ((long long)blockIdx.x * 16 + warp) * 8;
    if (base_node >= nnodes) return;
    int j0 = lane * 4;

    float4 bv = *reinterpret_cast<const float4*>(bias + j0);
    unsigned long long acc[16];
    unsigned long long b01, b23;
    asm("mov.b64 %0, {%1, %2};" : "=l"(b01) : "f"(bv.x), "f"(bv.y));
    asm("mov.b64 %0, {%1, %2};" : "=l"(b23) : "f"(bv.z), "f"(bv.w));
#pragma unroll
    for (int m = 0; m < 8; ++m) { acc[2 * m] = b01; acc[2 * m + 1] = b23; }

    for (int c = 0; c < 8; ++c) {
        const float* Asrc = (c < 4) ? A0 : A1;
        int koff = (c & 3) * 32;
        float areg[8];
#pragma unroll
        for (int m = 0; m < 8; ++m) {
            long long nd = base_node + m;
            if (nd >= nnodes) nd = nnodes - 1;
            areg[m] = Asrc[nd * DFEAT + koff + lane];
        }
        int krow = c * 32;
#pragma unroll 8
        for (int kk = 0; kk < 32; ++kk) {
            ulonglong2 wv = *reinterpret_cast<const ulonglong2*>(
                &sW[(krow + kk) * W_STRIDE + j0]);
#pragma unroll
            for (int m = 0; m < 8; ++m) {
                float a = __shfl_sync(0xffffffffu, areg[m], kk);
                unsigned long long aa = dup_f32x2(a);
                FFMA2(acc[2 * m], aa, wv.x, acc[2 * m]);
                FFMA2(acc[2 * m + 1], aa, wv.y, acc[2 * m + 1]);
            }
        }
    }

#pragma unroll
    for (int m = 0; m < 8; ++m) {
        long long nd = base_node + m;
        if (nd >= nnodes) break;
        float4 o;
        unpack_f32x2(acc[2 * m], o.x, o.y);
        unpack_f32x2(acc[2 * m + 1], o.z, o.w);
        if (relu) {
            o.x = fmaxf(o.x, 0.f); o.y = fmaxf(o.y, 0.f);
            o.z = fmaxf(o.z, 0.f); o.w = fmaxf(o.w, 0.f);
        }
        *reinterpret_cast<float4*>(out + nd * DFEAT + j0) = o;
    }
}

// ---------------- launch ----------------------------------------------------
extern "C" void kernel_launch(void* const* d_in, const int* in_sizes, int n_in,
                              void* d_out, int out_size) {
    const float* x   = (const float*)d_in[0];
    const int*   ew  = (const int*)d_in[1];   // edge words (int32 or int64 halves)
    const float* Wl1 = (const float*)d_in[2];
    const float* bl1 = (const float*)d_in[3];
    const float* Wr1 = (const float*)d_in[4];
    const float* Wl2 = (const float*)d_in[5];
    const float* bl2 = (const float*)d_in[6];
    const float* Wr2 = (const float*)d_in[7];
    float*       out = (float*)d_out;

    int n = in_sizes[0] / DFEAT;      // 100000
    int e = in_sizes[1] / 2;          // 1600000 (element count / 2 rows)

    void *p_mean_v, *p_h_v, *p_cursor_v;
    cudaGetSymbolAddress(&p_mean_v, g_mean);
    cudaGetSymbolAddress(&p_h_v, g_h);
    cudaGetSymbolAddress(&p_cursor_v, g_cursor);
    float* p_mean = (float*)p_mean_v;
    float* p_h = (float*)p_h_v;
    int* p_cursor = (int*)p_cursor_v;

    cudaFuncSetAttribute(sage_gemm_kernel,
                         cudaFuncAttributeMaxDynamicSharedMemorySize, GEMM_SMEM);

    int zb = (n + 255) / 256;
    int eb = (e + 255) / 256;
    int ab = (n + 7) / 8;             // 8 warps (256 threads) per block
    int gb = (n + 127) / 128;         // 128 nodes per GEMM CTA

    // ---- edge extraction (dtype-agnostic) ----
    detect_kernel<<<1, 1>>>(ew);
    convert_kernel<<<eb, 256>>>(ew, e, n);

    // ---- CSR build (shared by both layers) ----
    zero_int_kernel<<<zb, 256>>>(p_cursor, n);
    count_deg_kernel<<<eb, 256>>>(e);
    scan_kernel<<<1, 1024>>>(n);
    zero_int_kernel<<<zb, 256>>>(p_cursor, n);
    fill_csr_kernel<<<eb, 256>>>(e);

    // ---- layer 1 ----
    agg_mean_kernel<<<ab, 256>>>(x, n);
    sage_gemm_kernel<<<gb, 512, GEMM_SMEM>>>(p_mean, x, Wl1, Wr1, bl1, p_h, n, 1);

    // ---- layer 2 ----
    agg_mean_kernel<<<ab, 256>>>(p_h, n);
    sage_gemm_kernel<<<gb, 512, GEMM_SMEM>>>(p_mean, p_h, Wl2, Wr2, bl2, out, n, 0);
}